// round 3
// baseline (speedup 1.0000x reference)
#include <cuda_runtime.h>
#include <cuda_bf16.h>

// MIoU (buggy-faithful): answer = popcount(presence mask of classes 1..20 in y_pred) / 21.
// y_true irrelevant. Single block of 1024 threads: one int4/thread = 4096 elements in
// one DRAM latency window; presence mask is complete after round 1 with prob 1-1e-84.
// No cross-block comm, no atomics, no fences. Fallback: block grid-strides entire array.

#define FULL_MASK 0x001FFFFEu  // bits 1..20
#define NT 1024u

__global__ void __launch_bounds__(NT) k_miou(const int4* __restrict__ p, unsigned n4,
                                             const int* __restrict__ y, unsigned n,
                                             float* __restrict__ out) {
    __shared__ unsigned warp_m[NT / 32];
    __shared__ unsigned s_bm;

    const unsigned tid  = threadIdx.x;
    const unsigned lane = tid & 31u;
    const unsigned wid  = tid >> 5;

    unsigned m = 0u;

    // Scalar tail (n % 4 elements; zero for this shape, kept for generality).
    if (n4 * 4u + tid < n) m |= 1u << __ldcg(&y[n4 * 4u + tid]);

    const unsigned iters = (n4 + NT - 1u) / NT;
    for (unsigned it = 0; it < iters; ++it) {
        unsigned i = it * NT + tid;
        if (i < n4) {
            int4 v = __ldcg(&p[i]);  // values in [0,20]
            m |= (1u << v.x) | (1u << v.y) | (1u << v.z) | (1u << v.w);
        }

        // Block-wide mask; exit after round 1 in the overwhelmingly likely case.
        unsigned wm = __reduce_or_sync(0xffffffffu, m);
        if (lane == 0) warp_m[wid] = wm;
        __syncthreads();
        if (tid < 32) {
            unsigned b = __reduce_or_sync(0xffffffffu, warp_m[tid]);
            if (tid == 0) s_bm = b;
        }
        __syncthreads();
        if ((s_bm & FULL_MASK) == FULL_MASK) break;
    }

    if (tid == 0)
        out[0] = (float)__popc(s_bm & FULL_MASK) / 21.0f;
}

extern "C" void kernel_launch(void* const* d_in, const int* in_sizes, int n_in,
                              void* d_out, int out_size) {
    const int* y_pred = (const int*)d_in[0];
    const unsigned n  = (unsigned)in_sizes[0];
    const unsigned n4 = n / 4u;

    k_miou<<<1, NT>>>((const int4*)y_pred, n4, y_pred, n, (float*)d_out);
}

// round 4
// speedup vs baseline: 1.4211x; 1.4211x over previous
#include <cuda_runtime.h>
#include <cuda_bf16.h>

// MIoU (buggy-faithful): answer = popcount(presence mask of classes 1..20 in y_pred) / 21.
// y_true irrelevant. Presence is monotone: a single warp sampling 1024 elements
// (32 lanes x 8 int4, one MLP=8 latency window) sees every class with prob 1-3e-21.
// Zero barriers, zero smem, one warp. Fallback: warp grid-strides the rest (never taken).

#define FULL_MASK 0x001FFFFEu  // bits 1..20

__global__ void __launch_bounds__(32) k_miou(const int4* __restrict__ p, unsigned n4,
                                             const int* __restrict__ y, unsigned n,
                                             float* __restrict__ out) {
    const unsigned lane = threadIdx.x;
    unsigned m = 0u;

    // Fast path: 8 independent vector loads per lane, lane-interleaved (coalesced,
    // 4 KB contiguous = 1024 elements). All 8 overlap in one latency window.
    const unsigned FAST = 8u * 32u;  // int4s covered by fast path
    if (FAST <= n4) {
#pragma unroll
        for (unsigned j = 0; j < 8u; ++j) {
            int4 v = __ldcg(&p[j * 32u + lane]);  // values in [0,20]
            m |= (1u << v.x) | (1u << v.y) | (1u << v.z) | (1u << v.w);
        }
    }

    unsigned wm = __reduce_or_sync(0xffffffffu, m);

    if ((wm & FULL_MASK) != FULL_MASK) {
        // Fallback (prob ~3e-21 on this data; needed for arbitrary-input correctness):
        // warp grid-strides the remainder, re-checking as it goes.
        unsigned i = (FAST <= n4 ? FAST : 0u) + lane;
        for (; i < n4; i += 32u) {
            int4 v = __ldcg(&p[i]);
            m |= (1u << v.x) | (1u << v.y) | (1u << v.z) | (1u << v.w);
            if ((i & 1023u) >= 992u) {  // periodic completeness check
                wm = __reduce_or_sync(0xffffffffu, m);
                if ((wm & FULL_MASK) == FULL_MASK) break;
            }
        }
        // Scalar tail (n % 4 elements; zero for this shape, kept for generality).
        for (unsigned j = n4 * 4u + lane; j < n; j += 32u)
            m |= 1u << __ldcg(&y[j]);
        wm = __reduce_or_sync(0xffffffffu, m);
    }

    if (lane == 0)
        out[0] = (float)__popc(wm & FULL_MASK) / 21.0f;
}

extern "C" void kernel_launch(void* const* d_in, const int* in_sizes, int n_in,
                              void* d_out, int out_size) {
    const int* y_pred = (const int*)d_in[0];
    const unsigned n  = (unsigned)in_sizes[0];
    const unsigned n4 = n / 4u;

    k_miou<<<1, 32>>>((const int4*)y_pred, n4, y_pred, n, (float*)d_out);
}